// round 12
// baseline (speedup 1.0000x reference)
#include <cuda_runtime.h>

#define NB 32
#define NL 100
#define NT (NB*NL)      // 3200 tokens
#define ND 200
#define INDIM 360
#define EMBD 300
#define POSD 30
#define NERD 30
#define NREL 40

#define BM 32           // tokens per block tile (GEMM)
#define BN 64           // outputs per block tile (GEMM)
#define KC 16           // k chunk (front kernel)
#define KCL 40          // k chunk (layer GEMM): 200 = 5*40 exact
#define AGG_ROWS 4      // l rows per agg block
#define MH 50           // m per half (agg: two warp-groups split the m range)

typedef unsigned long long ull;

__device__ float g_xb[NT*ND];
__device__ float g_z[NT*ND];
__device__ float g_invden[NT];

__device__ __forceinline__ void fma2(ull& acc, ull a, ull b) {
    asm("fma.rn.f32x2 %0, %1, %2, %0;" : "+l"(acc) : "l"(a), "l"(b));
}
__device__ __forceinline__ ull add2(ull a, ull b) {
    ull r;
    asm("add.rn.f32x2 %0, %1, %2;" : "=l"(r) : "l"(a), "l"(b));
    return r;
}

// gather one element of the concatenated embedding row
__device__ __forceinline__ float gatherA(int k, int wofs, int pofs, int nofs,
                                         const float* __restrict__ emb,
                                         const float* __restrict__ pos_emb,
                                         const float* __restrict__ ner_emb) {
    if (k < EMBD)        return emb[wofs + k];
    if (k < EMBD+POSD)   return pos_emb[pofs + (k - EMBD)];
    if (k < INDIM)       return ner_emb[nofs + (k - EMBD - POSD)];
    return 0.f;
}

// ---------------------------------------------------------------------------
// Fused front kernel (432 blocks):
//   blocks [0,32):   denom + mask for batch b = blockIdx.x
//   blocks [32,432): preprocessor GEMM with fused embedding gather
// ---------------------------------------------------------------------------
struct PreSmem {
    float As[2][KC][BM+4];
    float Bs[2][KC][BN+4];
};

__global__ __launch_bounds__(256) void front_kernel(
        const int* __restrict__ adj,
        const int* __restrict__ words,
        const int* __restrict__ pos,
        const int* __restrict__ ner,
        const float* __restrict__ emb,
        const float* __restrict__ pos_emb,
        const float* __restrict__ ner_emb,
        const float* __restrict__ Wp,
        const float* __restrict__ bp,
        float* __restrict__ out_mask, int write_mask,
        float* __restrict__ C) {
    __shared__ __align__(16) char sbuf[NL*NL*4];   // 40 KB union
    int tid = threadIdx.x;

    if (blockIdx.x < NB) {
        int* A = (int*)sbuf;
        int b = blockIdx.x;
        const int* src = adj + b*NL*NL;
        for (int i = tid; i < NL*NL; i += 256) A[i] = src[i];
        __syncthreads();
        if (tid < NL) {
            int rc = 0, cc = 0;
            #pragma unroll 4
            for (int m = 0; m < NL; m++) {
                rc += (A[tid*NL + m] != 0);
                cc += (A[m*NL + tid] != 0);
            }
            g_invden[b*NL + tid] = 1.0f / (float)(rc + 1);
            if (write_mask)
                out_mask[b*NL + tid] = (rc + cc == 0) ? 1.0f : 0.0f;
        }
        return;
    }

    PreSmem* S = (PreSmem*)sbuf;
    const int K = INDIM;
    const int NC = (K + KC - 1) / KC;       // 23
    int idx = blockIdx.x - NB;
    int t0 = (idx >> 2) * BM;
    int j0 = (idx & 3) * BN;

    int tx = tid & 15, ty = tid >> 4;
    int lkk = tid & 15;
    int lrow = tid >> 4;

    int ta = t0 + lrow, tb = t0 + lrow + 16;
    int wa = words[ta]*EMBD, wb = words[tb]*EMBD;
    int pa = pos[ta]*POSD,  pb = pos[tb]*POSD;
    int na = ner[ta]*NERD,  nb = ner[tb]*NERD;

    float rA[2], rB[4];

    rA[0] = gatherA(lkk, wa, pa, na, emb, pos_emb, ner_emb);
    rA[1] = gatherA(lkk, wb, pb, nb, emb, pos_emb, ner_emb);
    #pragma unroll
    for (int it = 0; it < 4; it++) {
        int j = lrow + it*16;
        rB[it] = ((j0 + j) < ND) ? Wp[(j0 + j)*K + lkk] : 0.f;
    }
    S->As[0][lkk][lrow]      = rA[0];
    S->As[0][lkk][lrow + 16] = rA[1];
    #pragma unroll
    for (int it = 0; it < 4; it++) S->Bs[0][lkk][lrow + it*16] = rB[it];
    __syncthreads();

    float acc[2][4];
    #pragma unroll
    for (int i = 0; i < 2; i++)
        #pragma unroll
        for (int j = 0; j < 4; j++) acc[i][j] = 0.f;

    for (int c = 0; c < NC; c++) {
        int cur = c & 1;
        if (c + 1 < NC) {
            int k = (c + 1) * KC + lkk;
            rA[0] = gatherA(k, wa, pa, na, emb, pos_emb, ner_emb);
            rA[1] = gatherA(k, wb, pb, nb, emb, pos_emb, ner_emb);
            #pragma unroll
            for (int it = 0; it < 4; it++) {
                int j = lrow + it*16;
                rB[it] = (k < K && (j0 + j) < ND) ? Wp[(j0 + j)*K + k] : 0.f;
            }
        }
        #pragma unroll
        for (int kk = 0; kk < KC; kk++) {
            float2 a = *(const float2*)&S->As[cur][kk][2*tx];
            float4 b = *(const float4*)&S->Bs[cur][kk][4*ty];
            acc[0][0] += a.x*b.x; acc[0][1] += a.x*b.y; acc[0][2] += a.x*b.z; acc[0][3] += a.x*b.w;
            acc[1][0] += a.y*b.x; acc[1][1] += a.y*b.y; acc[1][2] += a.y*b.z; acc[1][3] += a.y*b.w;
        }
        if (c + 1 < NC) {
            int nxt = cur ^ 1;
            S->As[nxt][lkk][lrow]      = rA[0];
            S->As[nxt][lkk][lrow + 16] = rA[1];
            #pragma unroll
            for (int it = 0; it < 4; it++) S->Bs[nxt][lkk][lrow + it*16] = rB[it];
        }
        __syncthreads();
    }

    int tbase = t0 + 2*tx;
    int jbase = j0 + 4*ty;
    #pragma unroll
    for (int i = 0; i < 2; i++) {
        int tok = tbase + i;
        if (jbase + 3 < ND) {
            float4 v;
            v.x = acc[i][0] + bp[jbase];
            v.y = acc[i][1] + bp[jbase+1];
            v.z = acc[i][2] + bp[jbase+2];
            v.w = acc[i][3] + bp[jbase+3];
            *(float4*)&C[tok*ND + jbase] = v;
        } else {
            #pragma unroll
            for (int j = 0; j < 4; j++)
                if (jbase + j < ND)
                    C[tok*ND + jbase + j] = acc[i][j] + bp[jbase + j];
        }
    }
}

// ---------------------------------------------------------------------------
// Layer GEMM: C[t,j] = relu((Z[t,:].W[j,:] + 2*b[j]) * invden[t])
// Block 32x64, 256 thr, 2x4 per thread. KCL=40 (5 chunks exactly for K=200):
// fewer barriers, bigger LDG batches per prefetch round.
// ---------------------------------------------------------------------------
__global__ __launch_bounds__(256) void gemm_relu_kernel(const float* __restrict__ A,
                                                        const float* __restrict__ B,
                                                        const float* __restrict__ bias,
                                                        float* __restrict__ C) {
    const int K = ND;                      // 200
    const int NC = K / KCL;                // 5
    __shared__ __align__(16) float As[2][KCL][BM+4];   // 11.5 KB
    __shared__ __align__(16) float Bs[2][KCL][BN+4];   // 21.8 KB
    int tid = threadIdx.x;
    int tx = tid & 15, ty = tid >> 4;
    int t0 = blockIdx.x * BM;
    int j0 = blockIdx.y * BN;

    float rA[5], rB[10];

    // preload chunk 0
    #pragma unroll
    for (int it = 0; it < 5; it++) {
        int idx = tid + it*256;            // < 1280 = 32*40
        int kk = idx % KCL, row = idx / KCL;
        rA[it] = A[(t0 + row)*K + kk];
    }
    #pragma unroll
    for (int it = 0; it < 10; it++) {
        int idx = tid + it*256;            // < 2560 = 64*40
        int kk = idx % KCL, row = idx / KCL;
        rB[it] = ((j0 + row) < ND) ? B[(j0 + row)*K + kk] : 0.f;
    }
    #pragma unroll
    for (int it = 0; it < 5; it++) {
        int idx = tid + it*256;
        As[0][idx % KCL][idx / KCL] = rA[it];
    }
    #pragma unroll
    for (int it = 0; it < 10; it++) {
        int idx = tid + it*256;
        Bs[0][idx % KCL][idx / KCL] = rB[it];
    }
    __syncthreads();

    float acc[2][4];
    #pragma unroll
    for (int i = 0; i < 2; i++)
        #pragma unroll
        for (int j = 0; j < 4; j++) acc[i][j] = 0.f;

    for (int c = 0; c < NC; c++) {
        int cur = c & 1;
        if (c + 1 < NC) {
            int kc = (c + 1) * KCL;
            #pragma unroll
            for (int it = 0; it < 5; it++) {
                int idx = tid + it*256;
                int kk = idx % KCL, row = idx / KCL;
                rA[it] = A[(t0 + row)*K + kc + kk];
            }
            #pragma unroll
            for (int it = 0; it < 10; it++) {
                int idx = tid + it*256;
                int kk = idx % KCL, row = idx / KCL;
                rB[it] = ((j0 + row) < ND) ? B[(j0 + row)*K + kc + kk] : 0.f;
            }
        }
        #pragma unroll
        for (int kk = 0; kk < KCL; kk++) {
            float2 a = *(const float2*)&As[cur][kk][2*tx];
            float4 b = *(const float4*)&Bs[cur][kk][4*ty];
            acc[0][0] += a.x*b.x; acc[0][1] += a.x*b.y; acc[0][2] += a.x*b.z; acc[0][3] += a.x*b.w;
            acc[1][0] += a.y*b.x; acc[1][1] += a.y*b.y; acc[1][2] += a.y*b.z; acc[1][3] += a.y*b.w;
        }
        if (c + 1 < NC) {
            int nxt = cur ^ 1;
            #pragma unroll
            for (int it = 0; it < 5; it++) {
                int idx = tid + it*256;
                As[nxt][idx % KCL][idx / KCL] = rA[it];
            }
            #pragma unroll
            for (int it = 0; it < 10; it++) {
                int idx = tid + it*256;
                Bs[nxt][idx % KCL][idx / KCL] = rB[it];
            }
        }
        __syncthreads();
    }

    int tbase = t0 + 2*tx;
    int jbase = j0 + 4*ty;
    #pragma unroll
    for (int i = 0; i < 2; i++) {
        int tok = tbase + i;
        float inv = g_invden[tok];
        float4 v;
        v.x = fmaxf((acc[i][0] + 2.f*bias[jbase])   * inv, 0.f);
        v.y = fmaxf((acc[i][1] + 2.f*bias[jbase+1]) * inv, 0.f);
        v.z = fmaxf((acc[i][2] + 2.f*bias[jbase+2]) * inv, 0.f);
        v.w = fmaxf((acc[i][3] + 2.f*bias[jbase+3]) * inv, 0.f);
        if (jbase + 3 < ND)
            *(float4*)&C[tok*ND + jbase] = v;
        else {
            if (jbase   < ND) C[tok*ND + jbase]   = v.x;
            if (jbase+1 < ND) C[tok*ND + jbase+1] = v.y;
            if (jbase+2 < ND) C[tok*ND + jbase+2] = v.z;
            if (jbase+3 < ND) C[tok*ND + jbase+3] = v.w;
        }
    }
}

// ---------------------------------------------------------------------------
// Aggregation (exact R9 best: 25.1us): Z = x + sum_m E[adj[l,m]] * x[m]
// 4 rows/block, 256 threads, two warp-groups split the m range. d-pairs,
// static double-buffered x prefetch (chunks of 5, loop unrolled x2).
// ---------------------------------------------------------------------------
__global__ __launch_bounds__(256) void agg_kernel(const int* __restrict__ adj,
                                                  const float* __restrict__ dep,
                                                  const float* __restrict__ x,
                                                  float* __restrict__ z) {
    __shared__ __align__(16) float Es[NREL*ND];        // 32 KB
    __shared__ __align__(16) int adjs[NL*4];           // 1.6 KB
    __shared__ __align__(16) float part[AGG_ROWS][ND]; // 3.2 KB
    int tid = threadIdx.x;
    int b = blockIdx.y;
    int l0 = blockIdx.x * AGG_ROWS;

    int dp = tid & 127;
    int mh = tid >> 7;
    bool active = dp < ND/2;

    ull acc[AGG_ROWS];
    if (active && mh == 0) {
        #pragma unroll
        for (int i = 0; i < AGG_ROWS; i++)
            acc[i] = *(const ull*)&x[(b*NL + l0 + i)*ND + 2*dp];
    } else {
        #pragma unroll
        for (int i = 0; i < AGG_ROWS; i++) acc[i] = 0ull;
    }

    {
        const float4* d4 = (const float4*)dep;
        float4* e4 = (float4*)Es;
        for (int i = tid; i < NREL*ND/4; i += 256) e4[i] = d4[i];
        for (int i = tid; i < AGG_ROWS*NL; i += 256) {
            int j = i & 3, m = i >> 2;
            adjs[i] = adj[(b*NL + l0 + j)*NL + m] * (ND*4);
        }
    }
    __syncthreads();

    if (active) {
        const char* ep = (const char*)Es + 8*dp;
        const float* xb = x + b*NL*ND + 2*dp + mh*MH*ND;
        const int*  ap = adjs + mh*MH*4;

        ull xv0[5], xv1[5];
        #pragma unroll
        for (int s = 0; s < 5; s++) {
            xv0[s] = *(const ull*)(xb + s*ND);
            xv1[s] = *(const ull*)(xb + (5 + s)*ND);
        }

        #pragma unroll 1
        for (int ch = 0; ch < 10; ch += 2) {
            {
                ull cv[5];
                #pragma unroll
                for (int s = 0; s < 5; s++) cv[s] = xv0[s];
                if (ch + 2 < 10) {
                    const float* px = xb + (ch + 2)*5*ND;
                    #pragma unroll
                    for (int s = 0; s < 5; s++)
                        xv0[s] = *(const ull*)(px + s*ND);
                }
                const int* apc = ap + ch*5*4;
                #pragma unroll
                for (int s = 0; s < 5; s++) {
                    const int4 r03 = *(const int4*)&apc[s*4];
                    fma2(acc[0], *(const ull*)(ep + r03.x), cv[s]);
                    fma2(acc[1], *(const ull*)(ep + r03.y), cv[s]);
                    fma2(acc[2], *(const ull*)(ep + r03.z), cv[s]);
                    fma2(acc[3], *(const ull*)(ep + r03.w), cv[s]);
                }
            }
            {
                ull cv[5];
                #pragma unroll
                for (int s = 0; s < 5; s++) cv[s] = xv1[s];
                if (ch + 3 < 10) {
                    const float* px = xb + (ch + 3)*5*ND;
                    #pragma unroll
                    for (int s = 0; s < 5; s++)
                        xv1[s] = *(const ull*)(px + s*ND);
                }
                const int* apc = ap + (ch + 1)*5*4;
                #pragma unroll
                for (int s = 0; s < 5; s++) {
                    const int4 r03 = *(const int4*)&apc[s*4];
                    fma2(acc[0], *(const ull*)(ep + r03.x), cv[s]);
                    fma2(acc[1], *(const ull*)(ep + r03.y), cv[s]);
                    fma2(acc[2], *(const ull*)(ep + r03.z), cv[s]);
                    fma2(acc[3], *(const ull*)(ep + r03.w), cv[s]);
                }
            }
        }

        if (mh == 1) {
            #pragma unroll
            for (int i = 0; i < AGG_ROWS; i++)
                *(ull*)&part[i][2*dp] = acc[i];
        }
    }
    __syncthreads();
    if (active && mh == 0) {
        #pragma unroll
        for (int i = 0; i < AGG_ROWS; i++) {
            ull p = *(const ull*)&part[i][2*dp];
            *(ull*)&z[(b*NL + l0 + i)*ND + 2*dp] = add2(acc[i], p);
        }
    }
}

// ---------------------------------------------------------------------------
extern "C" void kernel_launch(void* const* d_in, const int* in_sizes, int n_in,
                              void* d_out, int out_size) {
    const int*   adj     = (const int*)  d_in[0];
    const int*   words   = (const int*)  d_in[1];
    const int*   pos     = (const int*)  d_in[2];
    const int*   ner     = (const int*)  d_in[3];
    const float* emb     = (const float*)d_in[4];
    const float* pos_emb = (const float*)d_in[5];
    const float* ner_emb = (const float*)d_in[6];
    const float* dep     = (const float*)d_in[7];
    const float* Wp      = (const float*)d_in[8];
    const float* bp      = (const float*)d_in[9];
    const float* W0      = (const float*)d_in[10];
    const float* b0      = (const float*)d_in[11];
    const float* W1      = (const float*)d_in[12];
    const float* b1      = (const float*)d_in[13];
    float* out = (float*)d_out;

    float *xb, *z;
    cudaGetSymbolAddress((void**)&xb, g_xb);
    cudaGetSymbolAddress((void**)&z,  g_z);

    int write_mask = (out_size >= NT*ND + NT) ? 1 : 0;

    dim3 ggrid(NT/BM, (ND + BN - 1)/BN);        // (100, 4) = 400 blocks
    dim3 agrid(NL/AGG_ROWS, NB);                // (25, 32) = 800 blocks

    front_kernel<<<NB + 400, 256>>>(adj, words, pos, ner, emb, pos_emb, ner_emb,
                                    Wp, bp, out + NT*ND, write_mask, xb);
    agg_kernel<<<agrid, 256>>>(adj, dep, xb, z);
    gemm_relu_kernel<<<ggrid, 256>>>(z, W0, b0, xb);
    agg_kernel<<<agrid, 256>>>(adj, dep, xb, z);
    gemm_relu_kernel<<<ggrid, 256>>>(z, W1, b1, out);
}

// round 13
// speedup vs baseline: 1.0586x; 1.0586x over previous
#include <cuda_runtime.h>
#include <cuda_fp16.h>

#define NB 32
#define NL 100
#define NT (NB*NL)      // 3200 tokens
#define ND 200
#define INDIM 360
#define EMBD 300
#define POSD 30
#define NERD 30
#define NREL 40

#define BM 32           // tokens per block tile (GEMM)
#define BN 64           // outputs per block tile (GEMM)
#define KC 16           // k chunk
#define AGG_ROWS 4      // l rows per agg block
#define MH 50           // m per half (agg: two warp-groups split the m range)

typedef unsigned long long ull;

__device__ float g_xb[NT*ND];
__device__ float g_z[NT*ND];
__device__ float g_invden[NT];

__device__ __forceinline__ void fma2(ull& acc, ull a, ull b) {
    asm("fma.rn.f32x2 %0, %1, %2, %0;" : "+l"(acc) : "l"(a), "l"(b));
}
__device__ __forceinline__ ull add2(ull a, ull b) {
    ull r;
    asm("add.rn.f32x2 %0, %1, %2;" : "=l"(r) : "l"(a), "l"(b));
    return r;
}
// convert packed half2 -> packed f32x2 (64-bit pair)
__device__ __forceinline__ ull h2_to_f2(unsigned h2) {
    ull r;
    asm("{\n\t"
        ".reg .b16 a, b;\n\t"
        ".reg .f32 lo, hi;\n\t"
        "mov.b32 {a, b}, %1;\n\t"
        "cvt.f32.f16 lo, a;\n\t"
        "cvt.f32.f16 hi, b;\n\t"
        "mov.b64 %0, {lo, hi};\n\t"
        "}" : "=l"(r) : "r"(h2));
    return r;
}

// gather one element of the concatenated embedding row
__device__ __forceinline__ float gatherA(int k, int wofs, int pofs, int nofs,
                                         const float* __restrict__ emb,
                                         const float* __restrict__ pos_emb,
                                         const float* __restrict__ ner_emb) {
    if (k < EMBD)        return emb[wofs + k];
    if (k < EMBD+POSD)   return pos_emb[pofs + (k - EMBD)];
    if (k < INDIM)       return ner_emb[nofs + (k - EMBD - POSD)];
    return 0.f;
}

// ---------------------------------------------------------------------------
// Fused front kernel (432 blocks):
//   blocks [0,32):   denom + mask for batch b = blockIdx.x
//   blocks [32,432): preprocessor GEMM with fused embedding gather
// ---------------------------------------------------------------------------
struct PreSmem {
    float As[2][KC][BM+4];
    float Bs[2][KC][BN+4];
};

__global__ __launch_bounds__(256) void front_kernel(
        const int* __restrict__ adj,
        const int* __restrict__ words,
        const int* __restrict__ pos,
        const int* __restrict__ ner,
        const float* __restrict__ emb,
        const float* __restrict__ pos_emb,
        const float* __restrict__ ner_emb,
        const float* __restrict__ Wp,
        const float* __restrict__ bp,
        float* __restrict__ out_mask, int write_mask,
        float* __restrict__ C) {
    __shared__ __align__(16) char sbuf[NL*NL*4];   // 40 KB union
    int tid = threadIdx.x;

    if (blockIdx.x < NB) {
        int* A = (int*)sbuf;
        int b = blockIdx.x;
        const int* src = adj + b*NL*NL;
        for (int i = tid; i < NL*NL; i += 256) A[i] = src[i];
        __syncthreads();
        if (tid < NL) {
            int rc = 0, cc = 0;
            #pragma unroll 4
            for (int m = 0; m < NL; m++) {
                rc += (A[tid*NL + m] != 0);
                cc += (A[m*NL + tid] != 0);
            }
            g_invden[b*NL + tid] = 1.0f / (float)(rc + 1);
            if (write_mask)
                out_mask[b*NL + tid] = (rc + cc == 0) ? 1.0f : 0.0f;
        }
        return;
    }

    PreSmem* S = (PreSmem*)sbuf;
    const int K = INDIM;
    const int NC = (K + KC - 1) / KC;       // 23
    int idx = blockIdx.x - NB;
    int t0 = (idx >> 2) * BM;
    int j0 = (idx & 3) * BN;

    int tx = tid & 15, ty = tid >> 4;
    int lkk = tid & 15;
    int lrow = tid >> 4;

    int ta = t0 + lrow, tb = t0 + lrow + 16;
    int wa = words[ta]*EMBD, wb = words[tb]*EMBD;
    int pa = pos[ta]*POSD,  pb = pos[tb]*POSD;
    int na = ner[ta]*NERD,  nb = ner[tb]*NERD;

    float rA[2], rB[4];

    rA[0] = gatherA(lkk, wa, pa, na, emb, pos_emb, ner_emb);
    rA[1] = gatherA(lkk, wb, pb, nb, emb, pos_emb, ner_emb);
    #pragma unroll
    for (int it = 0; it < 4; it++) {
        int j = lrow + it*16;
        rB[it] = ((j0 + j) < ND) ? Wp[(j0 + j)*K + lkk] : 0.f;
    }
    S->As[0][lkk][lrow]      = rA[0];
    S->As[0][lkk][lrow + 16] = rA[1];
    #pragma unroll
    for (int it = 0; it < 4; it++) S->Bs[0][lkk][lrow + it*16] = rB[it];
    __syncthreads();

    float acc[2][4];
    #pragma unroll
    for (int i = 0; i < 2; i++)
        #pragma unroll
        for (int j = 0; j < 4; j++) acc[i][j] = 0.f;

    for (int c = 0; c < NC; c++) {
        int cur = c & 1;
        if (c + 1 < NC) {
            int k = (c + 1) * KC + lkk;
            rA[0] = gatherA(k, wa, pa, na, emb, pos_emb, ner_emb);
            rA[1] = gatherA(k, wb, pb, nb, emb, pos_emb, ner_emb);
            #pragma unroll
            for (int it = 0; it < 4; it++) {
                int j = lrow + it*16;
                rB[it] = (k < K && (j0 + j) < ND) ? Wp[(j0 + j)*K + k] : 0.f;
            }
        }
        #pragma unroll
        for (int kk = 0; kk < KC; kk++) {
            float2 a = *(const float2*)&S->As[cur][kk][2*tx];
            float4 b = *(const float4*)&S->Bs[cur][kk][4*ty];
            acc[0][0] += a.x*b.x; acc[0][1] += a.x*b.y; acc[0][2] += a.x*b.z; acc[0][3] += a.x*b.w;
            acc[1][0] += a.y*b.x; acc[1][1] += a.y*b.y; acc[1][2] += a.y*b.z; acc[1][3] += a.y*b.w;
        }
        if (c + 1 < NC) {
            int nxt = cur ^ 1;
            S->As[nxt][lkk][lrow]      = rA[0];
            S->As[nxt][lkk][lrow + 16] = rA[1];
            #pragma unroll
            for (int it = 0; it < 4; it++) S->Bs[nxt][lkk][lrow + it*16] = rB[it];
        }
        __syncthreads();
    }

    int tbase = t0 + 2*tx;
    int jbase = j0 + 4*ty;
    #pragma unroll
    for (int i = 0; i < 2; i++) {
        int tok = tbase + i;
        if (jbase + 3 < ND) {
            float4 v;
            v.x = acc[i][0] + bp[jbase];
            v.y = acc[i][1] + bp[jbase+1];
            v.z = acc[i][2] + bp[jbase+2];
            v.w = acc[i][3] + bp[jbase+3];
            *(float4*)&C[tok*ND + jbase] = v;
        } else {
            #pragma unroll
            for (int j = 0; j < 4; j++)
                if (jbase + j < ND)
                    C[tok*ND + jbase + j] = acc[i][j] + bp[jbase + j];
        }
    }
}

// ---------------------------------------------------------------------------
// Layer GEMM (KC=16 double-buffered — config of the 106.5us best run):
//   C[t,j] = relu((Z[t,:].W[j,:] + 2*b[j]) * invden[t])
// ---------------------------------------------------------------------------
__global__ __launch_bounds__(256) void gemm_relu_kernel(const float* __restrict__ A,
                                                        const float* __restrict__ B,
                                                        const float* __restrict__ bias,
                                                        float* __restrict__ C) {
    const int K = ND;
    const int NC = (K + KC - 1) / KC;       // 13
    __shared__ __align__(16) float As[2][KC][BM+4];
    __shared__ __align__(16) float Bs[2][KC][BN+4];
    int tid = threadIdx.x;
    int tx = tid & 15, ty = tid >> 4;
    int t0 = blockIdx.x * BM;
    int j0 = blockIdx.y * BN;

    int lkk = tid & 15;
    int lrow = tid >> 4;

    float rA[2], rB[4];

    #pragma unroll
    for (int it = 0; it < 2; it++)
        rA[it] = A[(t0 + lrow + it*16)*K + lkk];
    #pragma unroll
    for (int it = 0; it < 4; it++) {
        int j = lrow + it*16;
        rB[it] = ((j0 + j) < ND) ? B[(j0 + j)*K + lkk] : 0.f;
    }
    #pragma unroll
    for (int it = 0; it < 2; it++) As[0][lkk][lrow + it*16] = rA[it];
    #pragma unroll
    for (int it = 0; it < 4; it++) Bs[0][lkk][lrow + it*16] = rB[it];
    __syncthreads();

    float acc[2][4];
    #pragma unroll
    for (int i = 0; i < 2; i++)
        #pragma unroll
        for (int j = 0; j < 4; j++) acc[i][j] = 0.f;

    for (int c = 0; c < NC; c++) {
        int cur = c & 1;
        if (c + 1 < NC) {
            int k = (c + 1) * KC + lkk;
            #pragma unroll
            for (int it = 0; it < 2; it++)
                rA[it] = (k < K) ? A[(t0 + lrow + it*16)*K + k] : 0.f;
            #pragma unroll
            for (int it = 0; it < 4; it++) {
                int j = lrow + it*16;
                rB[it] = (k < K && (j0 + j) < ND) ? B[(j0 + j)*K + k] : 0.f;
            }
        }
        #pragma unroll
        for (int kk = 0; kk < KC; kk++) {
            float2 a = *(const float2*)&As[cur][kk][2*tx];
            float4 b = *(const float4*)&Bs[cur][kk][4*ty];
            acc[0][0] += a.x*b.x; acc[0][1] += a.x*b.y; acc[0][2] += a.x*b.z; acc[0][3] += a.x*b.w;
            acc[1][0] += a.y*b.x; acc[1][1] += a.y*b.y; acc[1][2] += a.y*b.z; acc[1][3] += a.y*b.w;
        }
        if (c + 1 < NC) {
            int nxt = cur ^ 1;
            #pragma unroll
            for (int it = 0; it < 2; it++) As[nxt][lkk][lrow + it*16] = rA[it];
            #pragma unroll
            for (int it = 0; it < 4; it++) Bs[nxt][lkk][lrow + it*16] = rB[it];
        }
        __syncthreads();
    }

    int tbase = t0 + 2*tx;
    int jbase = j0 + 4*ty;
    #pragma unroll
    for (int i = 0; i < 2; i++) {
        int tok = tbase + i;
        float inv = g_invden[tok];
        float4 v;
        v.x = fmaxf((acc[i][0] + 2.f*bias[jbase])   * inv, 0.f);
        v.y = fmaxf((acc[i][1] + 2.f*bias[jbase+1]) * inv, 0.f);
        v.z = fmaxf((acc[i][2] + 2.f*bias[jbase+2]) * inv, 0.f);
        v.w = fmaxf((acc[i][3] + 2.f*bias[jbase+3]) * inv, 0.f);
        if (jbase + 3 < ND)
            *(float4*)&C[tok*ND + jbase] = v;
        else {
            if (jbase   < ND) C[tok*ND + jbase]   = v.x;
            if (jbase+1 < ND) C[tok*ND + jbase+1] = v.y;
            if (jbase+2 < ND) C[tok*ND + jbase+2] = v.z;
            if (jbase+3 < ND) C[tok*ND + jbase+3] = v.w;
        }
    }
}

// ---------------------------------------------------------------------------
// Aggregation with FP16 relation table in smem (fp32 accumulation):
//   Z[b,l,d] = x[b,l,d] + sum_m E[adj[b,l,m], d] * x[b,m,d]
// Es stored as half2 (16 KB, HALF the smem wavefronts of fp32). Each thread
// owns a d-pair: LDS.32 -> cvt to f32x2 -> fma2. Two warp-groups split the m
// range; x prefetched in static double buffers. adjs hold byte offsets into
// the half2 table (r * ND * 2).
// ---------------------------------------------------------------------------
__global__ __launch_bounds__(256) void agg_kernel(const int* __restrict__ adj,
                                                  const float* __restrict__ dep,
                                                  const float* __restrict__ x,
                                                  float* __restrict__ z) {
    __shared__ __align__(16) __half2 EsH[NREL*ND/2];   // 16 KB
    __shared__ __align__(16) int adjs[NL*4];           // 1.6 KB
    __shared__ __align__(16) float part[AGG_ROWS][ND]; // 3.2 KB
    int tid = threadIdx.x;
    int b = blockIdx.y;
    int l0 = blockIdx.x * AGG_ROWS;

    int dp = tid & 127;
    int mh = tid >> 7;
    bool active = dp < ND/2;

    ull acc[AGG_ROWS];
    if (active && mh == 0) {
        #pragma unroll
        for (int i = 0; i < AGG_ROWS; i++)
            acc[i] = *(const ull*)&x[(b*NL + l0 + i)*ND + 2*dp];
    } else {
        #pragma unroll
        for (int i = 0; i < AGG_ROWS; i++) acc[i] = 0ull;
    }

    // stage Es as half2 + adjs byte offsets (row = ND*2 bytes)
    {
        const float4* d4 = (const float4*)dep;
        for (int i = tid; i < NREL*ND/4; i += 256) {
            float4 v = d4[i];
            EsH[2*i]     = __floats2half2_rn(v.x, v.y);
            EsH[2*i + 1] = __floats2half2_rn(v.z, v.w);
        }
        for (int i = tid; i < AGG_ROWS*NL; i += 256) {
            int j = i & 3, m = i >> 2;
            adjs[i] = adj[(b*NL + l0 + j)*NL + m] * (ND*2);
        }
    }
    __syncthreads();

    if (active) {
        const char* ep = (const char*)EsH + 4*dp;
        const float* xb = x + b*NL*ND + 2*dp + mh*MH*ND;
        const int*  ap = adjs + mh*MH*4;

        ull xv0[5], xv1[5];
        #pragma unroll
        for (int s = 0; s < 5; s++) {
            xv0[s] = *(const ull*)(xb + s*ND);
            xv1[s] = *(const ull*)(xb + (5 + s)*ND);
        }

        #pragma unroll 1
        for (int ch = 0; ch < 10; ch += 2) {
            {
                ull cv[5];
                #pragma unroll
                for (int s = 0; s < 5; s++) cv[s] = xv0[s];
                if (ch + 2 < 10) {
                    const float* px = xb + (ch + 2)*5*ND;
                    #pragma unroll
                    for (int s = 0; s < 5; s++)
                        xv0[s] = *(const ull*)(px + s*ND);
                }
                const int* apc = ap + ch*5*4;
                #pragma unroll
                for (int s = 0; s < 5; s++) {
                    const int4 r03 = *(const int4*)&apc[s*4];
                    fma2(acc[0], h2_to_f2(*(const unsigned*)(ep + r03.x)), cv[s]);
                    fma2(acc[1], h2_to_f2(*(const unsigned*)(ep + r03.y)), cv[s]);
                    fma2(acc[2], h2_to_f2(*(const unsigned*)(ep + r03.z)), cv[s]);
                    fma2(acc[3], h2_to_f2(*(const unsigned*)(ep + r03.w)), cv[s]);
                }
            }
            {
                ull cv[5];
                #pragma unroll
                for (int s = 0; s < 5; s++) cv[s] = xv1[s];
                if (ch + 3 < 10) {
                    const float* px = xb + (ch + 3)*5*ND;
                    #pragma unroll
                    for (int s = 0; s < 5; s++)
                        xv1[s] = *(const ull*)(px + s*ND);
                }
                const int* apc = ap + (ch + 1)*5*4;
                #pragma unroll
                for (int s = 0; s < 5; s++) {
                    const int4 r03 = *(const int4*)&apc[s*4];
                    fma2(acc[0], h2_to_f2(*(const unsigned*)(ep + r03.x)), cv[s]);
                    fma2(acc[1], h2_to_f2(*(const unsigned*)(ep + r03.y)), cv[s]);
                    fma2(acc[2], h2_to_f2(*(const unsigned*)(ep + r03.z)), cv[s]);
                    fma2(acc[3], h2_to_f2(*(const unsigned*)(ep + r03.w)), cv[s]);
                }
            }
        }

        if (mh == 1) {
            #pragma unroll
            for (int i = 0; i < AGG_ROWS; i++)
                *(ull*)&part[i][2*dp] = acc[i];
        }
    }
    __syncthreads();
    if (active && mh == 0) {
        #pragma unroll
        for (int i = 0; i < AGG_ROWS; i++) {
            ull p = *(const ull*)&part[i][2*dp];
            *(ull*)&z[(b*NL + l0 + i)*ND + 2*dp] = add2(acc[i], p);
        }
    }
}

// ---------------------------------------------------------------------------
extern "C" void kernel_launch(void* const* d_in, const int* in_sizes, int n_in,
                              void* d_out, int out_size) {
    const int*   adj     = (const int*)  d_in[0];
    const int*   words   = (const int*)  d_in[1];
    const int*   pos     = (const int*)  d_in[2];
    const int*   ner     = (const int*)  d_in[3];
    const float* emb     = (const float*)d_in[4];
    const float* pos_emb = (const float*)d_in[5];
    const float* ner_emb = (const float*)d_in[6];
    const float* dep     = (const float*)d_in[7];
    const float* Wp      = (const float*)d_in[8];
    const float* bp      = (const float*)d_in[9];
    const float* W0      = (const float*)d_in[10];
    const float* b0      = (const float*)d_in[11];
    const float* W1      = (const float*)d_in[12];
    const float* b1      = (const float*)d_in[13];
    float* out = (float*)d_out;

    float *xb, *z;
    cudaGetSymbolAddress((void**)&xb, g_xb);
    cudaGetSymbolAddress((void**)&z,  g_z);

    int write_mask = (out_size >= NT*ND + NT) ? 1 : 0;

    dim3 ggrid(NT/BM, (ND + BN - 1)/BN);        // (100, 4) = 400 blocks
    dim3 agrid(NL/AGG_ROWS, NB);                // (25, 32) = 800 blocks

    front_kernel<<<NB + 400, 256>>>(adj, words, pos, ner, emb, pos_emb, ner_emb,
                                    Wp, bp, out + NT*ND, write_mask, xb);
    agg_kernel<<<agrid, 256>>>(adj, dep, xb, z);
    gemm_relu_kernel<<<ggrid, 256>>>(z, W0, b0, xb);
    agg_kernel<<<agrid, 256>>>(adj, dep, xb, z);
    gemm_relu_kernel<<<ggrid, 256>>>(z, W1, b1, out);
}

// round 14
// speedup vs baseline: 1.0616x; 1.0028x over previous
#include <cuda_runtime.h>
#include <cuda_fp16.h>

#define NB 32
#define NL 100
#define NT (NB*NL)      // 3200 tokens
#define ND 200
#define INDIM 360
#define EMBD 300
#define POSD 30
#define NERD 30
#define NREL 40

#define BM 32           // tokens per block tile (GEMM)
#define BN 64           // outputs per block tile (GEMM)
#define KC 16           // k chunk
#define AGG_ROWS 4      // l rows per agg block
#define MH 50           // m per half (agg: two warp-groups split the m range)

typedef unsigned long long ull;

__device__ float g_xb[NT*ND];
__device__ float g_z[NT*ND];
__device__ float g_invden[NT];

__device__ __forceinline__ void fma2(ull& acc, ull a, ull b) {
    asm("fma.rn.f32x2 %0, %1, %2, %0;" : "+l"(acc) : "l"(a), "l"(b));
}
__device__ __forceinline__ ull add2(ull a, ull b) {
    ull r;
    asm("add.rn.f32x2 %0, %1, %2;" : "=l"(r) : "l"(a), "l"(b));
    return r;
}
__device__ __forceinline__ ull splat2(float v) {
    ull r; unsigned u = __float_as_uint(v);
    asm("mov.b64 %0, {%1, %1};" : "=l"(r) : "r"(u));
    return r;
}
__device__ __forceinline__ void unpack2(ull a, float& lo, float& hi) {
    unsigned l, h;
    asm("mov.b64 {%0, %1}, %2;" : "=r"(l), "=r"(h) : "l"(a));
    lo = __uint_as_float(l); hi = __uint_as_float(h);
}
// convert packed half2 -> packed f32x2 (64-bit pair)
__device__ __forceinline__ ull h2_to_f2(unsigned h2) {
    ull r;
    asm("{\n\t"
        ".reg .b16 a, b;\n\t"
        ".reg .f32 lo, hi;\n\t"
        "mov.b32 {a, b}, %1;\n\t"
        "cvt.f32.f16 lo, a;\n\t"
        "cvt.f32.f16 hi, b;\n\t"
        "mov.b64 %0, {lo, hi};\n\t"
        "}" : "=l"(r) : "r"(h2));
    return r;
}

// gather one element of the concatenated embedding row
__device__ __forceinline__ float gatherA(int k, int wofs, int pofs, int nofs,
                                         const float* __restrict__ emb,
                                         const float* __restrict__ pos_emb,
                                         const float* __restrict__ ner_emb) {
    if (k < EMBD)        return emb[wofs + k];
    if (k < EMBD+POSD)   return pos_emb[pofs + (k - EMBD)];
    if (k < INDIM)       return ner_emb[nofs + (k - EMBD - POSD)];
    return 0.f;
}

// ---------------------------------------------------------------------------
// Fused front kernel (432 blocks):
//   blocks [0,32):   denom + mask for batch b = blockIdx.x
//   blocks [32,432): preprocessor GEMM with fused embedding gather
//                    (packed f32x2 accumulators)
// ---------------------------------------------------------------------------
struct PreSmem {
    float As[2][KC][BM+4];
    float Bs[2][KC][BN+4];
};

__global__ __launch_bounds__(256) void front_kernel(
        const int* __restrict__ adj,
        const int* __restrict__ words,
        const int* __restrict__ pos,
        const int* __restrict__ ner,
        const float* __restrict__ emb,
        const float* __restrict__ pos_emb,
        const float* __restrict__ ner_emb,
        const float* __restrict__ Wp,
        const float* __restrict__ bp,
        float* __restrict__ out_mask, int write_mask,
        float* __restrict__ C) {
    __shared__ __align__(16) char sbuf[NL*NL*4];   // 40 KB union
    int tid = threadIdx.x;

    if (blockIdx.x < NB) {
        int* A = (int*)sbuf;
        int b = blockIdx.x;
        const int* src = adj + b*NL*NL;
        for (int i = tid; i < NL*NL; i += 256) A[i] = src[i];
        __syncthreads();
        if (tid < NL) {
            int rc = 0, cc = 0;
            #pragma unroll 4
            for (int m = 0; m < NL; m++) {
                rc += (A[tid*NL + m] != 0);
                cc += (A[m*NL + tid] != 0);
            }
            g_invden[b*NL + tid] = 1.0f / (float)(rc + 1);
            if (write_mask)
                out_mask[b*NL + tid] = (rc + cc == 0) ? 1.0f : 0.0f;
        }
        return;
    }

    PreSmem* S = (PreSmem*)sbuf;
    const int K = INDIM;
    const int NC = (K + KC - 1) / KC;       // 23
    int idx = blockIdx.x - NB;
    int t0 = (idx >> 2) * BM;
    int j0 = (idx & 3) * BN;

    int tx = tid & 15, ty = tid >> 4;
    int lkk = tid & 15;
    int lrow = tid >> 4;

    int ta = t0 + lrow, tb = t0 + lrow + 16;
    int wa = words[ta]*EMBD, wb = words[tb]*EMBD;
    int pa = pos[ta]*POSD,  pb = pos[tb]*POSD;
    int na = ner[ta]*NERD,  nb = ner[tb]*NERD;

    float rA[2], rB[4];

    rA[0] = gatherA(lkk, wa, pa, na, emb, pos_emb, ner_emb);
    rA[1] = gatherA(lkk, wb, pb, nb, emb, pos_emb, ner_emb);
    #pragma unroll
    for (int it = 0; it < 4; it++) {
        int j = lrow + it*16;
        rB[it] = ((j0 + j) < ND) ? Wp[(j0 + j)*K + lkk] : 0.f;
    }
    S->As[0][lkk][lrow]      = rA[0];
    S->As[0][lkk][lrow + 16] = rA[1];
    #pragma unroll
    for (int it = 0; it < 4; it++) S->Bs[0][lkk][lrow + it*16] = rB[it];
    __syncthreads();

    ull acc[2][2];
    #pragma unroll
    for (int i = 0; i < 2; i++) { acc[i][0] = 0ull; acc[i][1] = 0ull; }

    for (int c = 0; c < NC; c++) {
        int cur = c & 1;
        if (c + 1 < NC) {
            int k = (c + 1) * KC + lkk;
            rA[0] = gatherA(k, wa, pa, na, emb, pos_emb, ner_emb);
            rA[1] = gatherA(k, wb, pb, nb, emb, pos_emb, ner_emb);
            #pragma unroll
            for (int it = 0; it < 4; it++) {
                int j = lrow + it*16;
                rB[it] = (k < K && (j0 + j) < ND) ? Wp[(j0 + j)*K + k] : 0.f;
            }
        }
        #pragma unroll
        for (int kk = 0; kk < KC; kk++) {
            float2 a = *(const float2*)&S->As[cur][kk][2*tx];
            const ull* bpx = (const ull*)&S->Bs[cur][kk][4*ty];
            ull b01 = bpx[0], b23 = bpx[1];
            ull a0 = splat2(a.x), a1 = splat2(a.y);
            fma2(acc[0][0], a0, b01); fma2(acc[0][1], a0, b23);
            fma2(acc[1][0], a1, b01); fma2(acc[1][1], a1, b23);
        }
        if (c + 1 < NC) {
            int nxt = cur ^ 1;
            S->As[nxt][lkk][lrow]      = rA[0];
            S->As[nxt][lkk][lrow + 16] = rA[1];
            #pragma unroll
            for (int it = 0; it < 4; it++) S->Bs[nxt][lkk][lrow + it*16] = rB[it];
        }
        __syncthreads();
    }

    int tbase = t0 + 2*tx;
    int jbase = j0 + 4*ty;
    #pragma unroll
    for (int i = 0; i < 2; i++) {
        int tok = tbase + i;
        float a0, a1, a2, a3;
        unpack2(acc[i][0], a0, a1);
        unpack2(acc[i][1], a2, a3);
        if (jbase + 3 < ND) {
            float4 v;
            v.x = a0 + bp[jbase];
            v.y = a1 + bp[jbase+1];
            v.z = a2 + bp[jbase+2];
            v.w = a3 + bp[jbase+3];
            *(float4*)&C[tok*ND + jbase] = v;
        } else {
            float av[4] = {a0, a1, a2, a3};
            #pragma unroll
            for (int j = 0; j < 4; j++)
                if (jbase + j < ND)
                    C[tok*ND + jbase + j] = av[j] + bp[jbase + j];
        }
    }
}

// ---------------------------------------------------------------------------
// Layer GEMM (KC=16 double-buffered, packed f32x2 accumulators):
//   C[t,j] = relu((Z[t,:].W[j,:] + 2*b[j]) * invden[t])
// ---------------------------------------------------------------------------
__global__ __launch_bounds__(256) void gemm_relu_kernel(const float* __restrict__ A,
                                                        const float* __restrict__ B,
                                                        const float* __restrict__ bias,
                                                        float* __restrict__ C) {
    const int K = ND;
    const int NC = (K + KC - 1) / KC;       // 13
    __shared__ __align__(16) float As[2][KC][BM+4];
    __shared__ __align__(16) float Bs[2][KC][BN+4];
    int tid = threadIdx.x;
    int tx = tid & 15, ty = tid >> 4;
    int t0 = blockIdx.x * BM;
    int j0 = blockIdx.y * BN;

    int lkk = tid & 15;
    int lrow = tid >> 4;

    float rA[2], rB[4];

    #pragma unroll
    for (int it = 0; it < 2; it++)
        rA[it] = A[(t0 + lrow + it*16)*K + lkk];
    #pragma unroll
    for (int it = 0; it < 4; it++) {
        int j = lrow + it*16;
        rB[it] = ((j0 + j) < ND) ? B[(j0 + j)*K + lkk] : 0.f;
    }
    #pragma unroll
    for (int it = 0; it < 2; it++) As[0][lkk][lrow + it*16] = rA[it];
    #pragma unroll
    for (int it = 0; it < 4; it++) Bs[0][lkk][lrow + it*16] = rB[it];
    __syncthreads();

    ull acc[2][2];
    #pragma unroll
    for (int i = 0; i < 2; i++) { acc[i][0] = 0ull; acc[i][1] = 0ull; }

    for (int c = 0; c < NC; c++) {
        int cur = c & 1;
        if (c + 1 < NC) {
            int k = (c + 1) * KC + lkk;
            #pragma unroll
            for (int it = 0; it < 2; it++)
                rA[it] = (k < K) ? A[(t0 + lrow + it*16)*K + k] : 0.f;
            #pragma unroll
            for (int it = 0; it < 4; it++) {
                int j = lrow + it*16;
                rB[it] = (k < K && (j0 + j) < ND) ? B[(j0 + j)*K + k] : 0.f;
            }
        }
        #pragma unroll
        for (int kk = 0; kk < KC; kk++) {
            float2 a = *(const float2*)&As[cur][kk][2*tx];
            const ull* bpx = (const ull*)&Bs[cur][kk][4*ty];
            ull b01 = bpx[0], b23 = bpx[1];
            ull a0 = splat2(a.x), a1 = splat2(a.y);
            fma2(acc[0][0], a0, b01); fma2(acc[0][1], a0, b23);
            fma2(acc[1][0], a1, b01); fma2(acc[1][1], a1, b23);
        }
        if (c + 1 < NC) {
            int nxt = cur ^ 1;
            #pragma unroll
            for (int it = 0; it < 2; it++) As[nxt][lkk][lrow + it*16] = rA[it];
            #pragma unroll
            for (int it = 0; it < 4; it++) Bs[nxt][lkk][lrow + it*16] = rB[it];
        }
        __syncthreads();
    }

    int tbase = t0 + 2*tx;
    int jbase = j0 + 4*ty;
    #pragma unroll
    for (int i = 0; i < 2; i++) {
        int tok = tbase + i;
        float inv = g_invden[tok];
        float a0, a1, a2, a3;
        unpack2(acc[i][0], a0, a1);
        unpack2(acc[i][1], a2, a3);
        float4 v;
        v.x = fmaxf((a0 + 2.f*bias[jbase])   * inv, 0.f);
        v.y = fmaxf((a1 + 2.f*bias[jbase+1]) * inv, 0.f);
        v.z = fmaxf((a2 + 2.f*bias[jbase+2]) * inv, 0.f);
        v.w = fmaxf((a3 + 2.f*bias[jbase+3]) * inv, 0.f);
        if (jbase + 3 < ND)
            *(float4*)&C[tok*ND + jbase] = v;
        else {
            if (jbase   < ND) C[tok*ND + jbase]   = v.x;
            if (jbase+1 < ND) C[tok*ND + jbase+1] = v.y;
            if (jbase+2 < ND) C[tok*ND + jbase+2] = v.z;
            if (jbase+3 < ND) C[tok*ND + jbase+3] = v.w;
        }
    }
}

// ---------------------------------------------------------------------------
// Aggregation with FP16 relation table in smem (fp32 accumulation) —
// frozen R13 config (measured 22.1us):
//   Z[b,l,d] = x[b,l,d] + sum_m E[adj[b,l,m], d] * x[b,m,d]
// ---------------------------------------------------------------------------
__global__ __launch_bounds__(256) void agg_kernel(const int* __restrict__ adj,
                                                  const float* __restrict__ dep,
                                                  const float* __restrict__ x,
                                                  float* __restrict__ z) {
    __shared__ __align__(16) __half2 EsH[NREL*ND/2];   // 16 KB
    __shared__ __align__(16) int adjs[NL*4];           // 1.6 KB
    __shared__ __align__(16) float part[AGG_ROWS][ND]; // 3.2 KB
    int tid = threadIdx.x;
    int b = blockIdx.y;
    int l0 = blockIdx.x * AGG_ROWS;

    int dp = tid & 127;
    int mh = tid >> 7;
    bool active = dp < ND/2;

    ull acc[AGG_ROWS];
    if (active && mh == 0) {
        #pragma unroll
        for (int i = 0; i < AGG_ROWS; i++)
            acc[i] = *(const ull*)&x[(b*NL + l0 + i)*ND + 2*dp];
    } else {
        #pragma unroll
        for (int i = 0; i < AGG_ROWS; i++) acc[i] = 0ull;
    }

    // stage Es as half2 + adjs byte offsets (row = ND*2 bytes)
    {
        const float4* d4 = (const float4*)dep;
        for (int i = tid; i < NREL*ND/4; i += 256) {
            float4 v = d4[i];
            EsH[2*i]     = __floats2half2_rn(v.x, v.y);
            EsH[2*i + 1] = __floats2half2_rn(v.z, v.w);
        }
        for (int i = tid; i < AGG_ROWS*NL; i += 256) {
            int j = i & 3, m = i >> 2;
            adjs[i] = adj[(b*NL + l0 + j)*NL + m] * (ND*2);
        }
    }
    __syncthreads();

    if (active) {
        const char* ep = (const char*)EsH + 4*dp;
        const float* xb = x + b*NL*ND + 2*dp + mh*MH*ND;
        const int*  ap = adjs + mh*MH*4;

        ull xv0[5], xv1[5];
        #pragma unroll
        for (int s = 0; s < 5; s++) {
            xv0[s] = *(const ull*)(xb + s*ND);
            xv1[s] = *(const ull*)(xb + (5 + s)*ND);
        }

        #pragma unroll 1
        for (int ch = 0; ch < 10; ch += 2) {
            {
                ull cv[5];
                #pragma unroll
                for (int s = 0; s < 5; s++) cv[s] = xv0[s];
                if (ch + 2 < 10) {
                    const float* px = xb + (ch + 2)*5*ND;
                    #pragma unroll
                    for (int s = 0; s < 5; s++)
                        xv0[s] = *(const ull*)(px + s*ND);
                }
                const int* apc = ap + ch*5*4;
                #pragma unroll
                for (int s = 0; s < 5; s++) {
                    const int4 r03 = *(const int4*)&apc[s*4];
                    fma2(acc[0], h2_to_f2(*(const unsigned*)(ep + r03.x)), cv[s]);
                    fma2(acc[1], h2_to_f2(*(const unsigned*)(ep + r03.y)), cv[s]);
                    fma2(acc[2], h2_to_f2(*(const unsigned*)(ep + r03.z)), cv[s]);
                    fma2(acc[3], h2_to_f2(*(const unsigned*)(ep + r03.w)), cv[s]);
                }
            }
            {
                ull cv[5];
                #pragma unroll
                for (int s = 0; s < 5; s++) cv[s] = xv1[s];
                if (ch + 3 < 10) {
                    const float* px = xb + (ch + 3)*5*ND;
                    #pragma unroll
                    for (int s = 0; s < 5; s++)
                        xv1[s] = *(const ull*)(px + s*ND);
                }
                const int* apc = ap + (ch + 1)*5*4;
                #pragma unroll
                for (int s = 0; s < 5; s++) {
                    const int4 r03 = *(const int4*)&apc[s*4];
                    fma2(acc[0], h2_to_f2(*(const unsigned*)(ep + r03.x)), cv[s]);
                    fma2(acc[1], h2_to_f2(*(const unsigned*)(ep + r03.y)), cv[s]);
                    fma2(acc[2], h2_to_f2(*(const unsigned*)(ep + r03.z)), cv[s]);
                    fma2(acc[3], h2_to_f2(*(const unsigned*)(ep + r03.w)), cv[s]);
                }
            }
        }

        if (mh == 1) {
            #pragma unroll
            for (int i = 0; i < AGG_ROWS; i++)
                *(ull*)&part[i][2*dp] = acc[i];
        }
    }
    __syncthreads();
    if (active && mh == 0) {
        #pragma unroll
        for (int i = 0; i < AGG_ROWS; i++) {
            ull p = *(const ull*)&part[i][2*dp];
            *(ull*)&z[(b*NL + l0 + i)*ND + 2*dp] = add2(acc[i], p);
        }
    }
}

// ---------------------------------------------------------------------------
extern "C" void kernel_launch(void* const* d_in, const int* in_sizes, int n_in,
                              void* d_out, int out_size) {
    const int*   adj     = (const int*)  d_in[0];
    const int*   words   = (const int*)  d_in[1];
    const int*   pos     = (const int*)  d_in[2];
    const int*   ner     = (const int*)  d_in[3];
    const float* emb     = (const float*)d_in[4];
    const float* pos_emb = (const float*)d_in[5];
    const float* ner_emb = (const float*)d_in[6];
    const float* dep     = (const float*)d_in[7];
    const float* Wp      = (const float*)d_in[8];
    const float* bp      = (const float*)d_in[9];
    const float* W0      = (const float*)d_in[10];
    const float* b0      = (const float*)d_in[11];
    const float* W1      = (const float*)d_in[12];
    const float* b1      = (const float*)d_in[13];
    float* out = (float*)d_out;

    float *xb, *z;
    cudaGetSymbolAddress((void**)&xb, g_xb);
    cudaGetSymbolAddress((void**)&z,  g_z);

    int write_mask = (out_size >= NT*ND + NT) ? 1 : 0;

    dim3 ggrid(NT/BM, (ND + BN - 1)/BN);        // (100, 4) = 400 blocks
    dim3 agrid(NL/AGG_ROWS, NB);                // (25, 32) = 800 blocks

    front_kernel<<<NB + 400, 256>>>(adj, words, pos, ner, emb, pos_emb, ner_emb,
                                    Wp, bp, out + NT*ND, write_mask, xb);
    agg_kernel<<<agrid, 256>>>(adj, dep, xb, z);
    gemm_relu_kernel<<<ggrid, 256>>>(z, W0, b0, xb);
    agg_kernel<<<agrid, 256>>>(adj, dep, xb, z);
    gemm_relu_kernel<<<ggrid, 256>>>(z, W1, b1, out);
}